// round 1
// baseline (speedup 1.0000x reference)
#include <cuda_runtime.h>
#include <math.h>

// Problem constants (fixed shapes per reference setup_inputs)
#define N_PER   3000
#define N       9000
#define IOU_THR 0.6f
#define CHUNKS  71              // ceil(9000/128)
#define WORDS   (CHUNKS * 4)    // 284 uint32 mask words per row (j/32 indexing)

// ---------------- scratch (static device arrays; no allocation) --------------
__device__ float    g_boxes[N * 4];    // concatenated, weighted-score order (original)
__device__ float    g_scores[N];
__device__ int      g_inv[N];          // inv permutation: g_inv[rank] = original idx
__device__ float    g_sboxes[N * 4];   // sorted by descending score
__device__ float    g_sscores[N];
__device__ unsigned g_mask[N * WORDS]; // IoU >= thr bitmask (sorted index space)
__device__ int      g_assign[N];       // cluster head (sorted idx) for each sorted box
__device__ float    g_sw[N];           // sum of member scores per head
__device__ int      g_cnt[N];          // cluster size per head
__device__ float    g_acc[N * 4];      // sum of score*box per head
__device__ float    g_key[N];          // fused score (or -inf for non-heads)
__device__ float    g_wbox[N * 4];     // fused boxes

#define NEG_INF __int_as_float(0xff800000)

// -------- 1. concat + per-model weight + accumulator init --------------------
__global__ void k_concat(const float* __restrict__ b0, const float* __restrict__ b1,
                         const float* __restrict__ b2, const float* __restrict__ s0,
                         const float* __restrict__ s1, const float* __restrict__ s2,
                         const float* __restrict__ w) {
    int i = blockIdx.x * blockDim.x + threadIdx.x;
    if (i >= N) return;
    int m = i / N_PER, r = i - m * N_PER;
    const float* b = (m == 0) ? b0 : (m == 1 ? b1 : b2);
    const float* s = (m == 0) ? s0 : (m == 1 ? s1 : s2);
    reinterpret_cast<float4*>(g_boxes)[i] = reinterpret_cast<const float4*>(b)[r];
    g_scores[i] = s[r] * w[m];
    g_sw[i] = 0.0f;
    g_cnt[i] = 0;
    reinterpret_cast<float4*>(g_acc)[i] = make_float4(0.f, 0.f, 0.f, 0.f);
}

// -------- 2. stable descending rank of scores (one warp per element) ---------
__global__ void k_rank_scores() {
    int gw   = (blockIdx.x * blockDim.x + threadIdx.x) >> 5;
    int lane = threadIdx.x & 31;
    if (gw >= N) return;
    float si = g_scores[gw];
    int c = 0;
    for (int j = lane; j < N; j += 32) {
        float sj = __ldg(&g_scores[j]);
        c += (sj > si) || (sj == si && j < gw);
    }
    #pragma unroll
    for (int o = 16; o; o >>= 1) c += __shfl_down_sync(0xffffffffu, c, o);
    if (lane == 0) g_inv[c] = gw;
}

// -------- 3. gather into sorted order ----------------------------------------
__global__ void k_gather() {
    int r = blockIdx.x * blockDim.x + threadIdx.x;
    if (r >= N) return;
    int i = g_inv[r];
    reinterpret_cast<float4*>(g_sboxes)[r] = reinterpret_cast<const float4*>(g_boxes)[i];
    g_sscores[r] = g_scores[i];
}

// -------- 4. IoU>=thr bitmask, one block per row -----------------------------
__global__ void k_mask() {
    int i = blockIdx.x;
    float4 bi = reinterpret_cast<const float4*>(g_sboxes)[i];
    float ai = (bi.z - bi.x) * (bi.w - bi.y);
    int t = threadIdx.x, w = t >> 5, lane = t & 31;
    for (int c = 0; c < CHUNKS; c++) {
        int j = c * 128 + t;
        bool p = false;
        if (j < N) {
            float4 bj = __ldg(reinterpret_cast<const float4*>(g_sboxes) + j);
            float aj = (bj.z - bj.x) * (bj.w - bj.y);
            float lx = fmaxf(bi.x, bj.x), ly = fmaxf(bi.y, bj.y);
            float rx = fminf(bi.z, bj.z), ry = fminf(bi.w, bj.w);
            float iw = fmaxf(rx - lx, 0.f), ih = fmaxf(ry - ly, 0.f);
            float inter = iw * ih;
            p = inter >= IOU_THR * (ai + aj - inter);
        }
        unsigned bal = __ballot_sync(0xffffffffu, p);
        if (lane == 0) g_mask[i * WORDS + c * 4 + w] = bal;
    }
}

// -------- 5. serial greedy suppression + earliest-head assignment ------------
// Single block; each thread owns one 32-bit remv word.
__global__ void k_suppress() {
    __shared__ unsigned remv[WORDS];
    int t = threadIdx.x;
    if (t < WORDS) remv[t] = 0u;
    __syncthreads();
    for (int i = 0; i < N; i++) {
        // state unchanged since last barrier -> all threads agree
        bool dead = (remv[i >> 5] >> (i & 31)) & 1u;
        if (dead) continue;
        unsigned row = (t < WORDS) ? g_mask[i * WORDS + t] : 0u;
        unsigned old = (t < WORDS) ? remv[t] : 0u;
        unsigned neu = row & ~old;
        __syncthreads();                 // all reads done before any write
        if (t < WORDS) remv[t] = old | row;
        while (neu) {
            int b = __ffs(neu) - 1;
            g_assign[t * 32 + b] = i;    // earliest head wins (processing order)
            neu &= neu - 1;
        }
        __syncthreads();                 // writes visible before next bit-test
    }
}

// -------- 6. per-cluster weighted accumulation -------------------------------
__global__ void k_accum() {
    int j = blockIdx.x * blockDim.x + threadIdx.x;
    if (j >= N) return;
    int h = g_assign[j];
    float s = g_sscores[j];
    float4 b = reinterpret_cast<const float4*>(g_sboxes)[j];
    atomicAdd(&g_sw[h], s);
    atomicAdd(&g_cnt[h], 1);
    atomicAdd(&g_acc[h * 4 + 0], s * b.x);
    atomicAdd(&g_acc[h * 4 + 1], s * b.y);
    atomicAdd(&g_acc[h * 4 + 2], s * b.z);
    atomicAdd(&g_acc[h * 4 + 3], s * b.w);
}

// -------- 7. fused score/box per head ----------------------------------------
__global__ void k_finalize(const float* __restrict__ w) {
    int i = blockIdx.x * blockDim.x + threadIdx.x;
    if (i >= N) return;
    float wsum  = w[0] + w[1] + w[2];
    float wmean = wsum * (1.0f / 3.0f);
    int c = g_cnt[i];
    if (c > 0) {
        float sw = g_sw[i];
        float4 a = reinterpret_cast<const float4*>(g_acc)[i];
        float inv = 1.0f / sw;
        reinterpret_cast<float4*>(g_wbox)[i] =
            make_float4(a.x * inv, a.y * inv, a.z * inv, a.w * inv);
        g_key[i] = sw / fmaxf(wsum, wmean * (float)c);
    } else {
        g_key[i] = NEG_INF;
    }
}

// -------- 8. rank by fused score (stable desc) + scatter to output -----------
__global__ void k_rank_out(float* __restrict__ out) {
    int gw   = (blockIdx.x * blockDim.x + threadIdx.x) >> 5;
    int lane = threadIdx.x & 31;
    if (gw >= N) return;
    float ki = g_key[gw];
    int c = 0;
    for (int j = lane; j < N; j += 32) {
        float kj = __ldg(&g_key[j]);
        c += (kj > ki) || (kj == ki && j < gw);
    }
    #pragma unroll
    for (int o = 16; o; o >>= 1) c += __shfl_down_sync(0xffffffffu, c, o);
    if (lane == 0) {
        int r = c;
        bool valid = (ki != NEG_INF);
        float4 b = valid ? reinterpret_cast<const float4*>(g_wbox)[gw]
                         : make_float4(0.f, 0.f, 0.f, 0.f);
        reinterpret_cast<float4*>(out)[r] = b;        // boxes at [0, 4N)
        out[4 * N + r] = valid ? ki : 0.0f;           // scores at [4N, 5N)
    }
}

extern "C" void kernel_launch(void* const* d_in, const int* in_sizes, int n_in,
                              void* d_out, int out_size) {
    const float* b0 = (const float*)d_in[0];
    const float* b1 = (const float*)d_in[1];
    const float* b2 = (const float*)d_in[2];
    const float* s0 = (const float*)d_in[3];
    const float* s1 = (const float*)d_in[4];
    const float* s2 = (const float*)d_in[5];
    const float* w  = (const float*)d_in[6];
    float* out = (float*)d_out;

    const int TB = 256;
    const int GB = (N + TB - 1) / TB;          // 36 blocks for per-element kernels
    const int GW = (N * 32 + TB - 1) / TB;     // 1125 blocks for warp-per-element

    k_concat<<<GB, TB>>>(b0, b1, b2, s0, s1, s2, w);
    k_rank_scores<<<GW, TB>>>();
    k_gather<<<GB, TB>>>();
    k_mask<<<N, 128>>>();
    k_suppress<<<1, 288>>>();
    k_accum<<<GB, TB>>>();
    k_finalize<<<GB, TB>>>(w);
    k_rank_out<<<GW, TB>>>(out);
}

// round 2
// speedup vs baseline: 19.4393x; 19.4393x over previous
#include <cuda_runtime.h>
#include <math.h>

// Problem constants (fixed shapes per reference setup_inputs)
#define N_PER   3000
#define N       9000
#define IOU_THR 0.6f
#define CAP     192            // max neighbors stored per box (avg degree ~1)

// ---------------- scratch (static device arrays; no allocation) --------------
__device__ float    g_boxes[N * 4];    // concatenated, weighted-score (original order)
__device__ float    g_scores[N];
__device__ int      g_inv[N];          // g_inv[rank] = original idx
__device__ float    g_sboxes[N * 4];   // sorted by descending score
__device__ float    g_sscores[N];
__device__ float    g_area[N];         // areas in sorted order
__device__ int      g_ncnt[N];         // neighbor count per box (sorted space)
__device__ int      g_nbr[N * CAP];    // neighbor lists (sorted space)
__device__ int      g_assign[N];       // cluster head (sorted idx) for each box
__device__ float    g_sw[N];           // sum of member scores per head
__device__ int      g_cnt[N];          // cluster size per head
__device__ float    g_acc[N * 4];      // sum of score*box per head
__device__ float    g_key[N];          // fused score (-inf for non-heads)
__device__ float    g_wbox[N * 4];     // fused boxes

#define NEG_INF __int_as_float(0xff800000)

// -------- 1. concat + per-model weight + scratch init ------------------------
__global__ void k_concat(const float* __restrict__ b0, const float* __restrict__ b1,
                         const float* __restrict__ b2, const float* __restrict__ s0,
                         const float* __restrict__ s1, const float* __restrict__ s2,
                         const float* __restrict__ w) {
    int i = blockIdx.x * blockDim.x + threadIdx.x;
    if (i >= N) return;
    int m = i / N_PER, r = i - m * N_PER;
    const float* b = (m == 0) ? b0 : (m == 1 ? b1 : b2);
    const float* s = (m == 0) ? s0 : (m == 1 ? s1 : s2);
    reinterpret_cast<float4*>(g_boxes)[i] = reinterpret_cast<const float4*>(b)[r];
    g_scores[i] = s[r] * w[m];
    g_ncnt[i]   = 0;
    g_assign[i] = i;             // default: own head (heads + isolated boxes)
    g_sw[i]     = 0.0f;
    g_cnt[i]    = 0;
    reinterpret_cast<float4*>(g_acc)[i] = make_float4(0.f, 0.f, 0.f, 0.f);
}

// -------- 2. stable descending rank of scores (one warp per element) ---------
__global__ void k_rank_scores() {
    int gw   = (blockIdx.x * blockDim.x + threadIdx.x) >> 5;
    int lane = threadIdx.x & 31;
    if (gw >= N) return;
    float si = g_scores[gw];
    int c = 0;
    for (int j = lane; j < N; j += 32) {
        float sj = __ldg(&g_scores[j]);
        c += (sj > si) || (sj == si && j < gw);
    }
    #pragma unroll
    for (int o = 16; o; o >>= 1) c += __shfl_down_sync(0xffffffffu, c, o);
    if (lane == 0) g_inv[c] = gw;
}

// -------- 3. gather into sorted order + precompute areas ---------------------
__global__ void k_gather() {
    int r = blockIdx.x * blockDim.x + threadIdx.x;
    if (r >= N) return;
    int i = g_inv[r];
    float4 b = reinterpret_cast<const float4*>(g_boxes)[i];
    reinterpret_cast<float4*>(g_sboxes)[r] = b;
    g_sscores[r] = g_scores[i];
    g_area[r] = (b.z - b.x) * (b.w - b.y);
}

// -------- 4. sparse IoU>=thr edges (j>i only, insert both directions) --------
__global__ void k_edges() {
    int i = blockIdx.x;
    float4 bi = reinterpret_cast<const float4*>(g_sboxes)[i];
    float ai = g_area[i];
    for (int j = i + 1 + threadIdx.x; j < N; j += blockDim.x) {
        float4 bj = __ldg(reinterpret_cast<const float4*>(g_sboxes) + j);
        float aj = __ldg(&g_area[j]);
        float lx = fmaxf(bi.x, bj.x), ly = fmaxf(bi.y, bj.y);
        float rx = fminf(bi.z, bj.z), ry = fminf(bi.w, bj.w);
        float iw = fmaxf(rx - lx, 0.f), ih = fmaxf(ry - ly, 0.f);
        float inter = iw * ih;
        if (inter >= IOU_THR * (ai + aj - inter)) {
            int ci = atomicAdd(&g_ncnt[i], 1);
            if (ci < CAP) g_nbr[i * CAP + ci] = j;
            int cj = atomicAdd(&g_ncnt[j], 1);
            if (cj < CAP) g_nbr[j * CAP + cj] = i;
        }
    }
}

// -------- 5. greedy-MIS heads via Jacobi fixed point + killer assignment -----
// head[i] = (no neighbor j<i is a head). Jacobi sweeps from all-1 converge to
// the unique fixed point (== sequential greedy) in <= dependency-depth sweeps.
// Killed box's cluster head = min-index head neighbor.
__global__ void k_resolve() {
    __shared__ unsigned char hA[N];
    __shared__ unsigned char hB[N];
    __shared__ unsigned char cnt8[N];
    __shared__ int changed;
    int t = threadIdx.x, nt = blockDim.x;

    for (int i = t; i < N; i += nt) {
        int c = g_ncnt[i];
        cnt8[i] = (unsigned char)(c > CAP ? CAP : c);
        hA[i] = 1;
        hB[i] = 1;
    }
    __syncthreads();

    unsigned char* cur = hA;
    unsigned char* nxt = hB;
    while (true) {
        if (t == 0) changed = 0;
        __syncthreads();
        for (int i = t; i < N; i += nt) {
            int c = cnt8[i];
            unsigned char h = 1;
            if (c) {
                const int* lst = &g_nbr[i * CAP];
                for (int k = 0; k < c; k++) {
                    int j = lst[k];
                    if (j < i && cur[j]) { h = 0; break; }
                }
            }
            nxt[i] = h;
            if (h != cur[i]) changed = 1;
        }
        __syncthreads();
        int done = !changed;                 // everyone reads before reset
        unsigned char* tmp = cur; cur = nxt; nxt = tmp;
        __syncthreads();
        if (done) break;
    }

    // cur = converged heads. Assign killed boxes to min-index head neighbor.
    for (int i = t; i < N; i += nt) {
        int c = cnt8[i];
        if (c && !cur[i]) {
            int m = N;
            const int* lst = &g_nbr[i * CAP];
            for (int k = 0; k < c; k++) {
                int j = lst[k];
                if (cur[j] && j < m) m = j;
            }
            g_assign[i] = m;
        }
        // heads and isolated boxes keep default g_assign[i] = i
    }
}

// -------- 6. per-cluster weighted accumulation -------------------------------
__global__ void k_accum() {
    int j = blockIdx.x * blockDim.x + threadIdx.x;
    if (j >= N) return;
    int h = g_assign[j];
    float s = g_sscores[j];
    float4 b = reinterpret_cast<const float4*>(g_sboxes)[j];
    atomicAdd(&g_sw[h], s);
    atomicAdd(&g_cnt[h], 1);
    atomicAdd(&g_acc[h * 4 + 0], s * b.x);
    atomicAdd(&g_acc[h * 4 + 1], s * b.y);
    atomicAdd(&g_acc[h * 4 + 2], s * b.z);
    atomicAdd(&g_acc[h * 4 + 3], s * b.w);
}

// -------- 7. fused score/box per head ----------------------------------------
__global__ void k_finalize(const float* __restrict__ w) {
    int i = blockIdx.x * blockDim.x + threadIdx.x;
    if (i >= N) return;
    float wsum  = w[0] + w[1] + w[2];
    float wmean = wsum * (1.0f / 3.0f);
    int c = g_cnt[i];
    if (c > 0) {
        float sw = g_sw[i];
        float4 a = reinterpret_cast<const float4*>(g_acc)[i];
        float inv = 1.0f / sw;
        reinterpret_cast<float4*>(g_wbox)[i] =
            make_float4(a.x * inv, a.y * inv, a.z * inv, a.w * inv);
        g_key[i] = sw / fmaxf(wsum, wmean * (float)c);
    } else {
        g_key[i] = NEG_INF;
    }
}

// -------- 8. rank by fused score (stable desc) + scatter to output -----------
__global__ void k_rank_out(float* __restrict__ out) {
    int gw   = (blockIdx.x * blockDim.x + threadIdx.x) >> 5;
    int lane = threadIdx.x & 31;
    if (gw >= N) return;
    float ki = g_key[gw];
    int c = 0;
    for (int j = lane; j < N; j += 32) {
        float kj = __ldg(&g_key[j]);
        c += (kj > ki) || (kj == ki && j < gw);
    }
    #pragma unroll
    for (int o = 16; o; o >>= 1) c += __shfl_down_sync(0xffffffffu, c, o);
    if (lane == 0) {
        int r = c;
        bool valid = (ki != NEG_INF);
        float4 b = valid ? reinterpret_cast<const float4*>(g_wbox)[gw]
                         : make_float4(0.f, 0.f, 0.f, 0.f);
        reinterpret_cast<float4*>(out)[r] = b;        // boxes at [0, 4N)
        out[4 * N + r] = valid ? ki : 0.0f;           // scores at [4N, 5N)
    }
}

extern "C" void kernel_launch(void* const* d_in, const int* in_sizes, int n_in,
                              void* d_out, int out_size) {
    const float* b0 = (const float*)d_in[0];
    const float* b1 = (const float*)d_in[1];
    const float* b2 = (const float*)d_in[2];
    const float* s0 = (const float*)d_in[3];
    const float* s1 = (const float*)d_in[4];
    const float* s2 = (const float*)d_in[5];
    const float* w  = (const float*)d_in[6];
    float* out = (float*)d_out;

    const int TB = 256;
    const int GB = (N + TB - 1) / TB;          // per-element kernels
    const int GW = (N * 32 + TB - 1) / TB;     // warp-per-element kernels

    k_concat<<<GB, TB>>>(b0, b1, b2, s0, s1, s2, w);
    k_rank_scores<<<GW, TB>>>();
    k_gather<<<GB, TB>>>();
    k_edges<<<N, 128>>>();
    k_resolve<<<1, 1024>>>();
    k_accum<<<GB, TB>>>();
    k_finalize<<<GB, TB>>>(w);
    k_rank_out<<<GW, TB>>>(out);
}